// round 14
// baseline (speedup 1.0000x reference)
#include <cuda_runtime.h>
#include <cuda_bf16.h>

#define BATCH 16
#define LEN   128
#define HID   128
#define G4    512   // 4*HID
#define EMB   128
#define D2    256   // 2*HID
#define HPAD  136   // padded h row: segments at +0 and +68 floats

typedef unsigned long long u64;

// ---------------- scratch (device globals; no allocation) ----------------
__device__ float g_xp [2*BATCH*LEN*G4];
__device__ float g_h0 [BATCH*LEN*D2];
__device__ float g_h1 [BATCH*LEN*D2];
__device__ float g_a  [BATCH*LEN*100];   // holds exp(-2*a)
__device__ float g_bp [BATCH*LEN*100];   // holds exp(-2*bp)

// ---------------- helpers ----------------
__device__ __forceinline__ float sigf(float x){
    float e = __expf(-x);
    return __fdividef(1.f, 1.f + e);
}
__device__ __forceinline__ float tanhf_(float x){
    float e = __expf(-2.f * x);
    return __fdividef(2.f, 1.f + e) - 1.f;
}
__device__ __forceinline__ void fma2(u64 &d, u64 a, u64 b){
    asm("fma.rn.f32x2 %0, %1, %2, %0;" : "+l"(d) : "l"(a), "l"(b));
}
__device__ __forceinline__ float2 unpack2(u64 v){
    float2 r; asm("mov.b64 {%0,%1}, %2;" : "=f"(r.x), "=f"(r.y) : "l"(v)); return r;
}
__device__ __forceinline__ unsigned smem_u32(const void* p){
    unsigned a;
    asm("{ .reg .u64 t; cvta.to.shared.u64 t, %1; cvt.u32.u64 %0, t; }" : "=r"(a) : "l"(p));
    return a;
}

// ---------------- tiled GEMM, proven FFMA body, f/b merged on z ----------------
// C[m][n] = A[m][0:K].W[n][0:K] + b1[n] + b2[n].
// expo:  store exp(-2*val) instead of val.
// do_emb: A ignored; A-tile gathered from word/tag embeddings (layer-0 fuse).
__global__ __launch_bounds__(256)
void gemm64(const float* __restrict__ A,
            const float* __restrict__ W0, const float* __restrict__ W1,
            const float* __restrict__ b1_0, const float* __restrict__ b1_1,
            const float* __restrict__ b2_0, const float* __restrict__ b2_1,
            float* __restrict__ C0, float* __restrict__ C1,
            int N, int K, int wstride, int expo, int do_emb,
            const int* __restrict__ widx, const int* __restrict__ pidx,
            const float* __restrict__ wemb, const float* __restrict__ temb)
{
    __shared__ float As[16][68];
    __shared__ float Ws[16][68];
    int z = blockIdx.z;
    const float* W  = z ? W1   : W0;
    const float* b1 = z ? b1_1 : b1_0;
    const float* b2 = z ? b2_1 : b2_0;
    float* C        = z ? C1   : C0;

    int tid = threadIdx.x;
    int tx = tid & 15, ty = tid >> 4;
    int m0 = blockIdx.y * 64, n0 = blockIdx.x * 64;
    int lrow = tid >> 2;
    int lk   = (tid & 3) * 4;

    int ew = 0, ep = 0;
    if (do_emb){
        int m = m0 + lrow;
        ew = widx[m];
        ep = pidx[m];
    }

    float acc[4][4];
    #pragma unroll
    for (int i = 0; i < 4; i++)
        #pragma unroll
        for (int j = 0; j < 4; j++) acc[i][j] = 0.f;

    for (int k0 = 0; k0 < K; k0 += 16){
        int ka = k0 + lk;
        float4 av;
        if (do_emb){
            if (ka < 100) av = *(const float4*)&wemb[(size_t)ew * 100 + ka];
            else          av = *(const float4*)&temb[(size_t)ep * 28 + (ka - 100)];
        } else {
            av = *(const float4*)&A[(size_t)(m0 + lrow) * K + ka];
        }
        int wn = n0 + lrow;
        float4 wv = make_float4(0.f,0.f,0.f,0.f);
        if (wn < N) wv = *(const float4*)&W[(size_t)wn * wstride + ka];
        As[lk+0][lrow] = av.x; As[lk+1][lrow] = av.y; As[lk+2][lrow] = av.z; As[lk+3][lrow] = av.w;
        Ws[lk+0][lrow] = wv.x; Ws[lk+1][lrow] = wv.y; Ws[lk+2][lrow] = wv.z; Ws[lk+3][lrow] = wv.w;
        __syncthreads();
        #pragma unroll
        for (int kk = 0; kk < 16; kk++){
            float4 a4 = *(const float4*)&As[kk][ty*4];
            float4 w4 = *(const float4*)&Ws[kk][tx*4];
            float av_[4] = {a4.x, a4.y, a4.z, a4.w};
            float wv_[4] = {w4.x, w4.y, w4.z, w4.w};
            #pragma unroll
            for (int i = 0; i < 4; i++)
                #pragma unroll
                for (int j = 0; j < 4; j++) acc[i][j] = fmaf(av_[i], wv_[j], acc[i][j]);
        }
        __syncthreads();
    }
    #pragma unroll
    for (int j = 0; j < 4; j++){
        int n = n0 + tx*4 + j;
        if (n >= N) continue;
        float bias = (b1 ? b1[n] : 0.f) + (b2 ? b2[n] : 0.f);
        #pragma unroll
        for (int i = 0; i < 4; i++){
            int m = m0 + ty*4 + i;
            float v = acc[i][j] + bias;
            C[(size_t)m * N + n] = expo ? __expf(-2.f * v) : v;
        }
    }
}

// ---------------- LSTM: split-wait (local FMA overlaps peer DSMEM flight) ----------------
// 2-CTA cluster per (dir,batch). Rank owns 64 units (256 gate rows). 512 thr:
// warp=tid>>5, l=tid&31, c=l&3, g=(l>>2)&3, q=l>>4 (k sub-block).
// Thread holds 16 local-unit k-pairs + 16 peer-unit k-pairs (64 regs).
// Step: [bar-guarded] local FMA -> trywait(peer mbar) -> peer FMA -> gates ->
// publish (local STS + DSMEM + arrive) -> bar.
__global__ __launch_bounds__(512, 1) __cluster_dims__(2, 1, 1)
void lstm_kernel(const float* __restrict__ xp,   // [2][B][L][512]
                 const float* __restrict__ whf,
                 const float* __restrict__ whb,
                 float* __restrict__ hcat)       // [B][L][256]
{
    __shared__ __align__(16) float hf[2][HPAD];
    __shared__ __align__(8)  u64   mbar[2];

    int tid  = threadIdx.x;
    int warp = tid >> 5;
    int l    = tid & 31;
    int c    = l & 3;
    int g    = (l >> 2) & 3;
    int q    = l >> 4;                 // 0/1: k sub-block within each 64-unit segment

    int rank = blockIdx.x & 1;
    int cid  = blockIdx.x >> 1;
    int dir  = cid >> 4;
    int b    = cid & 15;

    int u  = rank * 64 + warp * 4 + c;
    int r  = g * 128 + u;

    const float* wh = dir ? whb : whf;
    const u64* wrow = (const u64*)(wh + (size_t)r * HID);
    // local segment: units [rank*64, rank*64+64), this thread: k-pairs [rank*32+q*16, +16)
    // peer  segment: units [(rank^1)*64, ...),   this thread: k-pairs [(rank^1)*32+q*16, +16)
    u64 wl[16], wp[16];
    #pragma unroll
    for (int p = 0; p < 16; p++) wl[p] = wrow[rank * 32 + q * 16 + p];
    #pragma unroll
    for (int p = 0; p < 16; p++) wp[p] = wrow[(rank ^ 1) * 32 + q * 16 + p];

    unsigned h_lo[2], mb_lo[2], h_pe[2], mb_pe[2];
    h_lo[0] = smem_u32(&hf[0][0]); h_lo[1] = smem_u32(&hf[1][0]);
    mb_lo[0] = smem_u32(&mbar[0]); mb_lo[1] = smem_u32(&mbar[1]);
    int peer = rank ^ 1;
    #pragma unroll
    for (int i = 0; i < 2; i++){
        asm("mapa.shared::cluster.u32 %0, %1, %2;" : "=r"(h_pe[i])  : "r"(h_lo[i]),  "r"(peer));
        asm("mapa.shared::cluster.u32 %0, %1, %2;" : "=r"(mb_pe[i]) : "r"(mb_lo[i]), "r"(peer));
    }

    if (tid < 2 * HPAD) ((float*)hf)[tid] = 0.f;
    if (tid == 0){
        asm volatile("mbarrier.init.shared.b64 [%0], 16;" :: "r"(mb_lo[0]) : "memory");
        asm volatile("mbarrier.init.shared.b64 [%0], 16;" :: "r"(mb_lo[1]) : "memory");
    }
    __syncthreads();
    asm volatile("barrier.cluster.arrive.aligned;" ::: "memory");
    asm volatile("barrier.cluster.wait.aligned;"   ::: "memory");

    float cst = 0.f;
    int ph[2] = {0, 0};

    const float* xpd = xp + ((size_t)(dir * BATCH + b)) * LEN * G4 + r;
    bool  is_t = (g == 2);
    float act_m = is_t ? 2.f : 1.f;
    float act_b = is_t ? -1.f : 0.f;
    float pre_m = is_t ? 2.f : 1.f;

    int t  = dir ? (LEN - 1) : 0;
    int dt = dir ? -1 : 1;
    unsigned wr_off = (unsigned)(rank * 68 + warp * 4) * 4u;
    unsigned loc_base = (unsigned)(rank * 68);        // our segment in hf
    unsigned pee_base = (unsigned)((rank ^ 1) * 68);  // peer segment in hf

    float xg = xpd[t * G4];                       // prefetch step 0

    for (int s = 0; s < LEN; s++){
        float xg_next = (s < LEN - 1) ? xpd[(t + dt) * G4] : 0.f;
        int buf = s & 1;

        // ---- local-half FMA (needs only CTA-local publishes, guarded by bar) ----
        const ulonglong2* hl = (const ulonglong2*)(&hf[buf][loc_base + q * 32]);
        u64 a0 = 0ull, a1 = 0ull;
        #pragma unroll
        for (int i = 0; i < 8; i++){
            ulonglong2 hv = hl[i];
            fma2(a0, wl[2*i],   hv.x);
            fma2(a1, wl[2*i+1], hv.y);
        }

        // ---- wait for peer's step-s data (arrives posted during step s-1) ----
        if (s > 0){
            unsigned mba = mb_lo[buf];
            unsigned par = (unsigned)ph[buf];
            unsigned done;
            asm volatile(
                "{\n\t.reg .pred p;\n\t"
                "mbarrier.try_wait.parity.acquire.cluster.shared::cta.b64 p, [%1], %2;\n\t"
                "selp.b32 %0, 1, 0, p;\n\t}"
                : "=r"(done) : "r"(mba), "r"(par) : "memory");
            if (!done){
                asm volatile(
                    "{\n\t.reg .pred P1;\n\t"
                    "WL_%=:\n\t"
                    "mbarrier.try_wait.parity.acquire.cluster.shared::cta.b64 P1, [%0], %1, 0x989680;\n\t"
                    "@P1 bra.uni WD_%=;\n\t"
                    "bra.uni WL_%=;\n\t"
                    "WD_%=:\n\t}"
                    :: "r"(mba), "r"(par) : "memory");
            }
            ph[buf] ^= 1;
        }

        // ---- peer-half FMA ----
        const ulonglong2* hp = (const ulonglong2*)(&hf[buf][pee_base + q * 32]);
        u64 a2 = 0ull, a3 = 0ull;
        #pragma unroll
        for (int i = 0; i < 8; i++){
            ulonglong2 hv = hp[i];
            fma2(a2, wp[2*i],   hv.x);
            fma2(a3, wp[2*i+1], hv.y);
        }

        float2 p0 = unpack2(a0);
        float2 p1 = unpack2(a1);
        float2 p2 = unpack2(a2);
        float2 p3 = unpack2(a3);
        float ph_sum = ((p0.x + p0.y) + (p1.x + p1.y)) + ((p2.x + p2.y) + (p3.x + p3.y));
        if (q == 0) ph_sum += xg;
        float pre = ph_sum + __shfl_xor_sync(0xffffffffu, ph_sum, 16);

        float sv  = sigf(pre * pre_m);
        float val = fmaf(act_m, sv, act_b);

        float vi = __shfl_sync(0xffffffffu, val, c);
        float vf = __shfl_sync(0xffffffffu, val, 4 + c);
        float vg = __shfl_sync(0xffffffffu, val, 8 + c);
        float vo = __shfl_sync(0xffffffffu, val, 12 + c);

        cst = vf * cst + vi * vg;
        float hv = vo * tanhf_(cst);

        float h1v = __shfl_sync(0xffffffffu, hv, 1);
        float h2v = __shfl_sync(0xffffffffu, hv, 2);
        float h3v = __shfl_sync(0xffffffffu, hv, 3);
        int nb = buf ^ 1;
        if (l == 0){
            *(float4*)&hcat[((size_t)b * LEN + t) * D2 + dir * HID + rank * 64 + warp * 4] =
                make_float4(hv, h1v, h2v, h3v);
            if (s < LEN - 1){
                *(float4*)&hf[nb][rank * 68 + warp * 4] = make_float4(hv, h1v, h2v, h3v);
                asm volatile("st.shared::cluster.v4.f32 [%0], {%1,%2,%3,%4};"
                             :: "r"(h_pe[nb] + wr_off), "f"(hv), "f"(h1v), "f"(h2v), "f"(h3v)
                             : "memory");
                asm volatile("mbarrier.arrive.release.cluster.shared::cluster.b64 _, [%0];"
                             :: "r"(mb_pe[nb]) : "memory");
            }
        }
        if (s < LEN - 1)
            __syncthreads();      // local publish visibility + WAR for next step
        t += dt;
        xg = xg_next;
    }

    asm volatile("barrier.cluster.arrive.aligned;" ::: "memory");
    asm volatile("barrier.cluster.wait.aligned;"   ::: "memory");
}

// ---------------- biaffine scorer: tanh(a+bp) = 2/(1+e^-2a * e^-2bp) - 1 ----------------
__global__ __launch_bounds__(128)
void scores_kernel(const float* __restrict__ w2, const float* __restrict__ b2,
                   float* __restrict__ out)
{
    int i  = blockIdx.x;      // 0..127
    int bq = blockIdx.y;      // 0..3
    int j  = threadIdx.x;     // 0..127
    __shared__ float ea_sh[4][100];
    __shared__ float w2_sh[100];
    if (j < 100){
        w2_sh[j] = w2[j];
        #pragma unroll
        for (int bi = 0; bi < 4; bi++)
            ea_sh[bi][j] = g_a[((size_t)(bq*4+bi) * LEN + i) * 100 + j];
    }
    __syncthreads();
    float wsum = 0.f;
    #pragma unroll 4
    for (int k = 0; k < 100; k++) wsum += w2_sh[k];
    float base = b2[0] - wsum;                  // score = 2*acc - wsum + b2
    for (int bi = 0; bi < 4; bi++){
        int b = bq * 4 + bi;
        const float* ebr = g_bp + ((size_t)b * LEN + j) * 100;
        const float* ear = ea_sh[bi];
        float acc = 0.f;
        #pragma unroll 4
        for (int k = 0; k < 100; k++){
            float prod = ear[k] * ebr[k];
            acc = fmaf(w2_sh[k], __fdividef(1.f, 1.f + prod), acc);
        }
        out[(size_t)(i * LEN + j) * BATCH + b] = fmaf(2.f, acc, base);
    }
}

// ---------------- launch ----------------
extern "C" void kernel_launch(void* const* d_in, const int* in_sizes, int n_in,
                              void* d_out, int out_size)
{
    const int*   widx = (const int*)  d_in[0];
    const int*   pidx = (const int*)  d_in[1];
    const float* wemb = (const float*)d_in[4];
    const float* temb = (const float*)d_in[5];
    const float* w_ih_l0f = (const float*)d_in[6];
    const float* w_hh_l0f = (const float*)d_in[7];
    const float* b_ih_l0f = (const float*)d_in[8];
    const float* b_hh_l0f = (const float*)d_in[9];
    const float* w_ih_l0b = (const float*)d_in[10];
    const float* w_hh_l0b = (const float*)d_in[11];
    const float* b_ih_l0b = (const float*)d_in[12];
    const float* b_hh_l0b = (const float*)d_in[13];
    const float* w_ih_l1f = (const float*)d_in[14];
    const float* w_hh_l1f = (const float*)d_in[15];
    const float* b_ih_l1f = (const float*)d_in[16];
    const float* b_hh_l1f = (const float*)d_in[17];
    const float* w_ih_l1b = (const float*)d_in[18];
    const float* w_hh_l1b = (const float*)d_in[19];
    const float* b_ih_l1b = (const float*)d_in[20];
    const float* b_hh_l1b = (const float*)d_in[21];
    const float* fc1_w = (const float*)d_in[22];
    const float* fc1_b = (const float*)d_in[23];
    const float* fc2_w = (const float*)d_in[24];
    const float* fc2_b = (const float*)d_in[25];
    float* out = (float*)d_out;

    float *p_xp, *p_h0, *p_h1, *p_a, *p_bp;
    cudaGetSymbolAddress((void**)&p_xp,  g_xp);
    cudaGetSymbolAddress((void**)&p_h0,  g_h0);
    cudaGetSymbolAddress((void**)&p_h1,  g_h1);
    cudaGetSymbolAddress((void**)&p_a,   g_a);
    cudaGetSymbolAddress((void**)&p_bp,  g_bp);

    const int M = BATCH * LEN;   // 2048

    // layer 0 input projections with fused embedding gather, f+b in one launch
    gemm64<<<dim3(8, 32, 2), 256>>>(nullptr,
        w_ih_l0f, w_ih_l0b, b_ih_l0f, b_ih_l0b, b_hh_l0f, b_hh_l0b,
        p_xp, p_xp + (size_t)M*G4, G4, EMB, EMB, 0, 1, widx, pidx, wemb, temb);
    lstm_kernel<<<64, 512>>>(p_xp, w_hh_l0f, w_hh_l0b, p_h0);

    // layer 1
    gemm64<<<dim3(8, 32, 2), 256>>>(p_h0,
        w_ih_l1f, w_ih_l1b, b_ih_l1f, b_ih_l1b, b_hh_l1f, b_hh_l1b,
        p_xp, p_xp + (size_t)M*G4, G4, D2, D2, 0, 0, nullptr, nullptr, nullptr, nullptr);
    lstm_kernel<<<64, 512>>>(p_xp, w_hh_l1f, w_hh_l1b, p_h1);

    // fc1 split projections, epilogue stores exp(-2*val)
    gemm64<<<dim3(2, 32, 2), 256>>>(p_h1,
        fc1_w, fc1_w + D2, (const float*)nullptr, fc1_b,
        (const float*)nullptr, (const float*)nullptr,
        p_a, p_bp, 100, D2, 512, 1, 0, nullptr, nullptr, nullptr, nullptr);

    // scores
    scores_kernel<<<dim3(128, 4), 128>>>(fc2_w, fc2_b, out);
    (void)in_sizes; (void)n_in; (void)out_size;
}

// round 15
// speedup vs baseline: 1.0504x; 1.0504x over previous
#include <cuda_runtime.h>
#include <cuda_bf16.h>

#define BATCH 16
#define LEN   128
#define HID   128
#define G4    512   // 4*HID
#define EMB   128
#define D2    256   // 2*HID
#define HPAD  136   // padded h row: halves at +0 and +68 floats

typedef unsigned long long u64;

// ---------------- scratch (device globals; no allocation) ----------------
__device__ float g_xp [2*BATCH*LEN*G4];
__device__ float g_h0 [BATCH*LEN*D2];
__device__ float g_h1 [BATCH*LEN*D2];
__device__ float g_a  [BATCH*LEN*100];   // holds exp(-2*a)
__device__ float g_bp [BATCH*LEN*100];   // holds exp(-2*bp)

// ---------------- helpers ----------------
__device__ __forceinline__ float sigf(float x){
    float e = __expf(-x);
    return __fdividef(1.f, 1.f + e);
}
__device__ __forceinline__ float tanhf_(float x){
    float e = __expf(-2.f * x);
    return __fdividef(2.f, 1.f + e) - 1.f;
}
__device__ __forceinline__ void fma2(u64 &d, u64 a, u64 b){
    asm("fma.rn.f32x2 %0, %1, %2, %0;" : "+l"(d) : "l"(a), "l"(b));
}
__device__ __forceinline__ float2 unpack2(u64 v){
    float2 r; asm("mov.b64 {%0,%1}, %2;" : "=f"(r.x), "=f"(r.y) : "l"(v)); return r;
}
__device__ __forceinline__ u64 dup2(float v){
    u64 r; asm("mov.b64 %0, {%1,%1};" : "=l"(r) : "f"(v)); return r;
}
__device__ __forceinline__ unsigned smem_u32(const void* p){
    unsigned a;
    asm("{ .reg .u64 t; cvta.to.shared.u64 t, %1; cvt.u32.u64 %0, t; }" : "=r"(a) : "l"(p));
    return a;
}

// ---------------- tiled GEMM: proven layout + register-dup FMA2 inner loop ----------------
// C[m][n] = A[m][0:K].W[n][0:K] + b1[n] + b2[n].
// expo:  store exp(-2*val) instead of val.
// do_emb: A ignored; A-tile gathered from word/tag embeddings (layer-0 fuse).
// Smem layout and load pattern identical to the proven FFMA version; only the
// compute loop changes: W broadcast duplicated into u64 in REGISTERS, m packed
// as f32x2 pairs from As -> 8 FMA2 + 4 MOV per kk instead of 16 FFMA.
__global__ __launch_bounds__(256)
void gemm64(const float* __restrict__ A,
            const float* __restrict__ W0, const float* __restrict__ W1,
            const float* __restrict__ b1_0, const float* __restrict__ b1_1,
            const float* __restrict__ b2_0, const float* __restrict__ b2_1,
            float* __restrict__ C0, float* __restrict__ C1,
            int N, int K, int wstride, int expo, int do_emb,
            const int* __restrict__ widx, const int* __restrict__ pidx,
            const float* __restrict__ wemb, const float* __restrict__ temb)
{
    __shared__ __align__(16) float As[16][68];
    __shared__ __align__(16) float Ws[16][68];
    int z = blockIdx.z;
    const float* W  = z ? W1   : W0;
    const float* b1 = z ? b1_1 : b1_0;
    const float* b2 = z ? b2_1 : b2_0;
    float* C        = z ? C1   : C0;

    int tid = threadIdx.x;
    int tx = tid & 15, ty = tid >> 4;
    int m0 = blockIdx.y * 64, n0 = blockIdx.x * 64;
    int lrow = tid >> 2;
    int lk   = (tid & 3) * 4;

    int ew = 0, ep = 0;
    if (do_emb){
        int m = m0 + lrow;
        ew = widx[m];
        ep = pidx[m];
    }

    u64 acc[2][4];                      // [m-pair][n], f32x2 over m
    #pragma unroll
    for (int i = 0; i < 2; i++)
        #pragma unroll
        for (int j = 0; j < 4; j++) acc[i][j] = 0ull;

    for (int k0 = 0; k0 < K; k0 += 16){
        int ka = k0 + lk;
        float4 av;
        if (do_emb){
            if (ka < 100) av = *(const float4*)&wemb[(size_t)ew * 100 + ka];
            else          av = *(const float4*)&temb[(size_t)ep * 28 + (ka - 100)];
        } else {
            av = *(const float4*)&A[(size_t)(m0 + lrow) * K + ka];
        }
        int wn = n0 + lrow;
        float4 wv = make_float4(0.f,0.f,0.f,0.f);
        if (wn < N) wv = *(const float4*)&W[(size_t)wn * wstride + ka];
        As[lk+0][lrow] = av.x; As[lk+1][lrow] = av.y; As[lk+2][lrow] = av.z; As[lk+3][lrow] = av.w;
        Ws[lk+0][lrow] = wv.x; Ws[lk+1][lrow] = wv.y; Ws[lk+2][lrow] = wv.z; Ws[lk+3][lrow] = wv.w;
        __syncthreads();
        #pragma unroll
        for (int kk = 0; kk < 16; kk++){
            ulonglong2 am = *(const ulonglong2*)&As[kk][ty*4];   // m pairs (ty*4, ty*4+2)
            float4 w4 = *(const float4*)&Ws[kk][tx*4];
            u64 w0 = dup2(w4.x), w1 = dup2(w4.y), w2 = dup2(w4.z), w3 = dup2(w4.w);
            fma2(acc[0][0], am.x, w0); fma2(acc[0][1], am.x, w1);
            fma2(acc[0][2], am.x, w2); fma2(acc[0][3], am.x, w3);
            fma2(acc[1][0], am.y, w0); fma2(acc[1][1], am.y, w1);
            fma2(acc[1][2], am.y, w2); fma2(acc[1][3], am.y, w3);
        }
        __syncthreads();
    }
    #pragma unroll
    for (int j = 0; j < 4; j++){
        int n = n0 + tx*4 + j;
        if (n >= N) continue;
        float bias = (b1 ? b1[n] : 0.f) + (b2 ? b2[n] : 0.f);
        #pragma unroll
        for (int i = 0; i < 2; i++){
            float2 v = unpack2(acc[i][j]);
            int m = m0 + ty*4 + i*2;
            float v0 = v.x + bias, v1 = v.y + bias;
            C[(size_t)m     * N + n] = expo ? __expf(-2.f * v0) : v0;
            C[(size_t)(m+1) * N + n] = expo ? __expf(-2.f * v1) : v1;
        }
    }
}

// ---------------- LSTM: R13 structure (best measured, 160us) ----------------
// 2-CTA cluster per (dir,batch). Rank owns 64 hidden units (256 gate rows).
// 512 threads: warp=tid>>5, l=tid&31, c=l&3, g=(l>>2)&3, half=l>>4.
// unit u = rank*64 + warp*4 + c ; row r = g*128 + u; 64 k (half) in 32 u64 regs.
__global__ __launch_bounds__(512, 1) __cluster_dims__(2, 1, 1)
void lstm_kernel(const float* __restrict__ xp,   // [2][B][L][512]
                 const float* __restrict__ whf,
                 const float* __restrict__ whb,
                 float* __restrict__ hcat)       // [B][L][256]
{
    __shared__ __align__(16) float hf[2][HPAD];
    __shared__ __align__(8)  u64   mbar[2];

    int tid  = threadIdx.x;
    int warp = tid >> 5;
    int l    = tid & 31;
    int c    = l & 3;
    int g    = (l >> 2) & 3;
    int half = l >> 4;

    int rank = blockIdx.x & 1;
    int cid  = blockIdx.x >> 1;
    int dir  = cid >> 4;
    int b    = cid & 15;

    int u  = rank * 64 + warp * 4 + c;
    int r  = g * 128 + u;

    const float* wh = dir ? whb : whf;
    const u64* wrow = (const u64*)(wh + (size_t)r * HID) + half * 32;
    u64 wr[32];
    #pragma unroll
    for (int p = 0; p < 32; p++) wr[p] = wrow[p];

    unsigned h_lo[2], mb_lo[2], h_pe[2], mb_pe[2];
    h_lo[0] = smem_u32(&hf[0][0]); h_lo[1] = smem_u32(&hf[1][0]);
    mb_lo[0] = smem_u32(&mbar[0]); mb_lo[1] = smem_u32(&mbar[1]);
    int peer = rank ^ 1;
    #pragma unroll
    for (int i = 0; i < 2; i++){
        asm("mapa.shared::cluster.u32 %0, %1, %2;" : "=r"(h_pe[i])  : "r"(h_lo[i]),  "r"(peer));
        asm("mapa.shared::cluster.u32 %0, %1, %2;" : "=r"(mb_pe[i]) : "r"(mb_lo[i]), "r"(peer));
    }

    if (tid < 2 * HPAD) ((float*)hf)[tid] = 0.f;
    if (tid == 0){
        asm volatile("mbarrier.init.shared.b64 [%0], 16;" :: "r"(mb_lo[0]) : "memory");
        asm volatile("mbarrier.init.shared.b64 [%0], 16;" :: "r"(mb_lo[1]) : "memory");
    }
    __syncthreads();
    asm volatile("barrier.cluster.arrive.aligned;" ::: "memory");
    asm volatile("barrier.cluster.wait.aligned;"   ::: "memory");

    float cst = 0.f;
    int ph[2] = {0, 0};

    const float* xpd = xp + ((size_t)(dir * BATCH + b)) * LEN * G4 + r;
    bool  is_t = (g == 2);
    float act_m = is_t ? 2.f : 1.f;
    float act_b = is_t ? -1.f : 0.f;
    float pre_m = is_t ? 2.f : 1.f;

    int t  = dir ? (LEN - 1) : 0;
    int dt = dir ? -1 : 1;
    unsigned wr_off = (unsigned)(rank * 68 + warp * 4) * 4u;

    float xg = xpd[t * G4];                       // prefetch step 0

    for (int s = 0; s < LEN; s++){
        float xg_next = (s < LEN - 1) ? xpd[(t + dt) * G4] : 0.f;

        const ulonglong2* hb = (const ulonglong2*)(&hf[s & 1][half * 68]);
        u64 a0 = 0ull, a1 = 0ull;
        #pragma unroll
        for (int i = 0; i < 16; i++){
            ulonglong2 hv = hb[i];
            fma2(a0, wr[2*i],   hv.x);
            fma2(a1, wr[2*i+1], hv.y);
        }
        float2 p0 = unpack2(a0);
        float2 p1 = unpack2(a1);
        float ph_sum = (p0.x + p0.y) + (p1.x + p1.y);
        if (half == 0) ph_sum += xg;
        float pre = ph_sum + __shfl_xor_sync(0xffffffffu, ph_sum, 16);

        float sv  = sigf(pre * pre_m);
        float val = fmaf(act_m, sv, act_b);

        float vi = __shfl_sync(0xffffffffu, val, c);
        float vf = __shfl_sync(0xffffffffu, val, 4 + c);
        float vg = __shfl_sync(0xffffffffu, val, 8 + c);
        float vo = __shfl_sync(0xffffffffu, val, 12 + c);

        cst = vf * cst + vi * vg;
        float hv = vo * tanhf_(cst);

        float h1v = __shfl_sync(0xffffffffu, hv, 1);
        float h2v = __shfl_sync(0xffffffffu, hv, 2);
        float h3v = __shfl_sync(0xffffffffu, hv, 3);
        int nb = (s & 1) ^ 1;
        if (l == 0){
            *(float4*)&hcat[((size_t)b * LEN + t) * D2 + dir * HID + rank * 64 + warp * 4] =
                make_float4(hv, h1v, h2v, h3v);
            if (s < LEN - 1){
                *(float4*)&hf[nb][rank * 68 + warp * 4] = make_float4(hv, h1v, h2v, h3v);
                asm volatile("st.shared::cluster.v4.f32 [%0], {%1,%2,%3,%4};"
                             :: "r"(h_pe[nb] + wr_off), "f"(hv), "f"(h1v), "f"(h2v), "f"(h3v)
                             : "memory");
                asm volatile("mbarrier.arrive.release.cluster.shared::cluster.b64 _, [%0];"
                             :: "r"(mb_pe[nb]) : "memory");
            }
        }
        if (s < LEN - 1){
            __syncthreads();
            unsigned mba = mb_lo[nb];
            unsigned par = (unsigned)ph[nb];
            unsigned done;
            asm volatile(
                "{\n\t.reg .pred p;\n\t"
                "mbarrier.try_wait.parity.acquire.cluster.shared::cta.b64 p, [%1], %2;\n\t"
                "selp.b32 %0, 1, 0, p;\n\t}"
                : "=r"(done) : "r"(mba), "r"(par) : "memory");
            if (!done){
                asm volatile(
                    "{\n\t.reg .pred P1;\n\t"
                    "WL_%=:\n\t"
                    "mbarrier.try_wait.parity.acquire.cluster.shared::cta.b64 P1, [%0], %1, 0x989680;\n\t"
                    "@P1 bra.uni WD_%=;\n\t"
                    "bra.uni WL_%=;\n\t"
                    "WD_%=:\n\t}"
                    :: "r"(mba), "r"(par) : "memory");
            }
            ph[nb] ^= 1;
        }
        t += dt;
        xg = xg_next;
    }

    asm volatile("barrier.cluster.arrive.aligned;" ::: "memory");
    asm volatile("barrier.cluster.wait.aligned;"   ::: "memory");
}

// ---------------- biaffine scorer: tanh(a+bp) = 2/(1+e^-2a * e^-2bp) - 1 ----------------
__global__ __launch_bounds__(128)
void scores_kernel(const float* __restrict__ w2, const float* __restrict__ b2,
                   float* __restrict__ out)
{
    int i  = blockIdx.x;      // 0..127
    int bq = blockIdx.y;      // 0..3
    int j  = threadIdx.x;     // 0..127
    __shared__ float ea_sh[4][100];
    __shared__ float w2_sh[100];
    if (j < 100){
        w2_sh[j] = w2[j];
        #pragma unroll
        for (int bi = 0; bi < 4; bi++)
            ea_sh[bi][j] = g_a[((size_t)(bq*4+bi) * LEN + i) * 100 + j];
    }
    __syncthreads();
    float wsum = 0.f;
    #pragma unroll 4
    for (int k = 0; k < 100; k++) wsum += w2_sh[k];
    float base = b2[0] - wsum;                  // score = 2*acc - wsum + b2
    for (int bi = 0; bi < 4; bi++){
        int b = bq * 4 + bi;
        const float* ebr = g_bp + ((size_t)b * LEN + j) * 100;
        const float* ear = ea_sh[bi];
        float acc = 0.f;
        #pragma unroll 4
        for (int k = 0; k < 100; k++){
            float prod = ear[k] * ebr[k];
            acc = fmaf(w2_sh[k], __fdividef(1.f, 1.f + prod), acc);
        }
        out[(size_t)(i * LEN + j) * BATCH + b] = fmaf(2.f, acc, base);
    }
}

// ---------------- launch ----------------
extern "C" void kernel_launch(void* const* d_in, const int* in_sizes, int n_in,
                              void* d_out, int out_size)
{
    const int*   widx = (const int*)  d_in[0];
    const int*   pidx = (const int*)  d_in[1];
    const float* wemb = (const float*)d_in[4];
    const float* temb = (const float*)d_in[5];
    const float* w_ih_l0f = (const float*)d_in[6];
    const float* w_hh_l0f = (const float*)d_in[7];
    const float* b_ih_l0f = (const float*)d_in[8];
    const float* b_hh_l0f = (const float*)d_in[9];
    const float* w_ih_l0b = (const float*)d_in[10];
    const float* w_hh_l0b = (const float*)d_in[11];
    const float* b_ih_l0b = (const float*)d_in[12];
    const float* b_hh_l0b = (const float*)d_in[13];
    const float* w_ih_l1f = (const float*)d_in[14];
    const float* w_hh_l1f = (const float*)d_in[15];
    const float* b_ih_l1f = (const float*)d_in[16];
    const float* b_hh_l1f = (const float*)d_in[17];
    const float* w_ih_l1b = (const float*)d_in[18];
    const float* w_hh_l1b = (const float*)d_in[19];
    const float* b_ih_l1b = (const float*)d_in[20];
    const float* b_hh_l1b = (const float*)d_in[21];
    const float* fc1_w = (const float*)d_in[22];
    const float* fc1_b = (const float*)d_in[23];
    const float* fc2_w = (const float*)d_in[24];
    const float* fc2_b = (const float*)d_in[25];
    float* out = (float*)d_out;

    float *p_xp, *p_h0, *p_h1, *p_a, *p_bp;
    cudaGetSymbolAddress((void**)&p_xp,  g_xp);
    cudaGetSymbolAddress((void**)&p_h0,  g_h0);
    cudaGetSymbolAddress((void**)&p_h1,  g_h1);
    cudaGetSymbolAddress((void**)&p_a,   g_a);
    cudaGetSymbolAddress((void**)&p_bp,  g_bp);

    const int M = BATCH * LEN;   // 2048

    // layer 0 input projections with fused embedding gather, f+b in one launch
    gemm64<<<dim3(8, 32, 2), 256>>>(nullptr,
        w_ih_l0f, w_ih_l0b, b_ih_l0f, b_ih_l0b, b_hh_l0f, b_hh_l0b,
        p_xp, p_xp + (size_t)M*G4, G4, EMB, EMB, 0, 1, widx, pidx, wemb, temb);
    lstm_kernel<<<64, 512>>>(p_xp, w_hh_l0f, w_hh_l0b, p_h0);

    // layer 1
    gemm64<<<dim3(8, 32, 2), 256>>>(p_h0,
        w_ih_l1f, w_ih_l1b, b_ih_l1f, b_ih_l1b, b_hh_l1f, b_hh_l1b,
        p_xp, p_xp + (size_t)M*G4, G4, D2, D2, 0, 0, nullptr, nullptr, nullptr, nullptr);
    lstm_kernel<<<64, 512>>>(p_xp, w_hh_l1f, w_hh_l1b, p_h1);

    // fc1 split projections, epilogue stores exp(-2*val)
    gemm64<<<dim3(2, 32, 2), 256>>>(p_h1,
        fc1_w, fc1_w + D2, (const float*)nullptr, fc1_b,
        (const float*)nullptr, (const float*)nullptr,
        p_a, p_bp, 100, D2, 512, 1, 0, nullptr, nullptr, nullptr, nullptr);

    // scores
    scores_kernel<<<dim3(128, 4), 128>>>(fc2_w, fc2_b, out);
    (void)in_sizes; (void)n_in; (void)out_size;
}

// round 16
// speedup vs baseline: 1.0562x; 1.0055x over previous
#include <cuda_runtime.h>
#include <cuda_bf16.h>

#define BATCH 16
#define LEN   128
#define HID   128
#define G4    512   // 4*HID
#define EMB   128
#define D2    256   // 2*HID
#define HPAD  136   // padded h row: halves at +0 and +68 floats

typedef unsigned long long u64;

// ---------------- scratch (device globals; no allocation) ----------------
__device__ float g_xp [2*BATCH*LEN*G4];
__device__ float g_h0 [BATCH*LEN*D2];
__device__ float g_h1 [BATCH*LEN*D2];
__device__ float g_a  [BATCH*LEN*100];   // holds exp(-2*a)
__device__ float g_bp [BATCH*LEN*100];   // holds exp(-2*bp)

// ---------------- helpers ----------------
__device__ __forceinline__ float sigf(float x){
    float e = __expf(-x);
    return __fdividef(1.f, 1.f + e);
}
__device__ __forceinline__ float tanhf_(float x){
    float e = __expf(-2.f * x);
    return __fdividef(2.f, 1.f + e) - 1.f;
}
__device__ __forceinline__ void fma2(u64 &d, u64 a, u64 b){
    asm("fma.rn.f32x2 %0, %1, %2, %0;" : "+l"(d) : "l"(a), "l"(b));
}
__device__ __forceinline__ float2 unpack2(u64 v){
    float2 r; asm("mov.b64 {%0,%1}, %2;" : "=f"(r.x), "=f"(r.y) : "l"(v)); return r;
}
__device__ __forceinline__ u64 dup2(float v){
    u64 r; asm("mov.b64 %0, {%1,%1};" : "=l"(r) : "f"(v)); return r;
}
__device__ __forceinline__ unsigned smem_u32(const void* p){
    unsigned a;
    asm("{ .reg .u64 t; cvta.to.shared.u64 t, %1; cvt.u32.u64 %0, t; }" : "=r"(a) : "l"(p));
    return a;
}

// ---------------- tiled GEMM: proven layout + register-dup FMA2 inner loop ----------------
// C[m][n] = A[m][0:K].W[n][0:K] + b1[n] + b2[n].
// expo:  store exp(-2*val).  do_emb: A-tile gathered from embeddings.
// PDL: waits on upstream grid before first A read; triggers after stores.
__global__ __launch_bounds__(256)
void gemm64(const float* __restrict__ A,
            const float* __restrict__ W0, const float* __restrict__ W1,
            const float* __restrict__ b1_0, const float* __restrict__ b1_1,
            const float* __restrict__ b2_0, const float* __restrict__ b2_1,
            float* __restrict__ C0, float* __restrict__ C1,
            int N, int K, int wstride, int expo, int do_emb,
            const int* __restrict__ widx, const int* __restrict__ pidx,
            const float* __restrict__ wemb, const float* __restrict__ temb)
{
    __shared__ __align__(16) float As[16][68];
    __shared__ __align__(16) float Ws[16][68];
    int z = blockIdx.z;
    const float* W  = z ? W1   : W0;
    const float* b1 = z ? b1_1 : b1_0;
    const float* b2 = z ? b2_1 : b2_0;
    float* C        = z ? C1   : C0;

    int tid = threadIdx.x;
    int tx = tid & 15, ty = tid >> 4;
    int m0 = blockIdx.y * 64, n0 = blockIdx.x * 64;
    int lrow = tid >> 2;
    int lk   = (tid & 3) * 4;

    // wait for producer grid before touching A / embeddings-independent inputs done
    cudaGridDependencySynchronize();

    int ew = 0, ep = 0;
    if (do_emb){
        int m = m0 + lrow;
        ew = widx[m];
        ep = pidx[m];
    }

    u64 acc[2][4];                      // [m-pair][n], f32x2 over m
    #pragma unroll
    for (int i = 0; i < 2; i++)
        #pragma unroll
        for (int j = 0; j < 4; j++) acc[i][j] = 0ull;

    for (int k0 = 0; k0 < K; k0 += 16){
        int ka = k0 + lk;
        float4 av;
        if (do_emb){
            if (ka < 100) av = *(const float4*)&wemb[(size_t)ew * 100 + ka];
            else          av = *(const float4*)&temb[(size_t)ep * 28 + (ka - 100)];
        } else {
            av = *(const float4*)&A[(size_t)(m0 + lrow) * K + ka];
        }
        int wn = n0 + lrow;
        float4 wv = make_float4(0.f,0.f,0.f,0.f);
        if (wn < N) wv = *(const float4*)&W[(size_t)wn * wstride + ka];
        As[lk+0][lrow] = av.x; As[lk+1][lrow] = av.y; As[lk+2][lrow] = av.z; As[lk+3][lrow] = av.w;
        Ws[lk+0][lrow] = wv.x; Ws[lk+1][lrow] = wv.y; Ws[lk+2][lrow] = wv.z; Ws[lk+3][lrow] = wv.w;
        __syncthreads();
        #pragma unroll
        for (int kk = 0; kk < 16; kk++){
            ulonglong2 am = *(const ulonglong2*)&As[kk][ty*4];   // m pairs (ty*4, ty*4+2)
            float4 w4 = *(const float4*)&Ws[kk][tx*4];
            u64 w0 = dup2(w4.x), w1 = dup2(w4.y), w2 = dup2(w4.z), w3 = dup2(w4.w);
            fma2(acc[0][0], am.x, w0); fma2(acc[0][1], am.x, w1);
            fma2(acc[0][2], am.x, w2); fma2(acc[0][3], am.x, w3);
            fma2(acc[1][0], am.y, w0); fma2(acc[1][1], am.y, w1);
            fma2(acc[1][2], am.y, w2); fma2(acc[1][3], am.y, w3);
        }
        __syncthreads();
    }
    #pragma unroll
    for (int j = 0; j < 4; j++){
        int n = n0 + tx*4 + j;
        if (n >= N) continue;
        float bias = (b1 ? b1[n] : 0.f) + (b2 ? b2[n] : 0.f);
        #pragma unroll
        for (int i = 0; i < 2; i++){
            float2 v = unpack2(acc[i][j]);
            int m = m0 + ty*4 + i*2;
            float v0 = v.x + bias, v1 = v.y + bias;
            C[(size_t)m     * N + n] = expo ? __expf(-2.f * v0) : v0;
            C[(size_t)(m+1) * N + n] = expo ? __expf(-2.f * v1) : v1;
        }
    }
    cudaTriggerProgrammaticLaunchCompletion();
}

// ---------------- LSTM: R13/R15 structure (best measured) + PDL ----------------
// 2-CTA cluster per (dir,batch). Rank owns 64 hidden units (256 gate rows).
// 512 threads: warp=tid>>5, l=tid&31, c=l&3, g=(l>>2)&3, half=l>>4.
// unit u = rank*64 + warp*4 + c ; row r = g*128 + u; 64 k (half) in 32 u64 regs.
// PDL: weight loads + mbar init + cluster sync run BEFORE the dependency sync;
// xp is first read only after cudaGridDependencySynchronize().
__global__ __launch_bounds__(512, 1) __cluster_dims__(2, 1, 1)
void lstm_kernel(const float* __restrict__ xp,   // [2][B][L][512]
                 const float* __restrict__ whf,
                 const float* __restrict__ whb,
                 float* __restrict__ hcat)       // [B][L][256]
{
    __shared__ __align__(16) float hf[2][HPAD];
    __shared__ __align__(8)  u64   mbar[2];

    int tid  = threadIdx.x;
    int warp = tid >> 5;
    int l    = tid & 31;
    int c    = l & 3;
    int g    = (l >> 2) & 3;
    int half = l >> 4;

    int rank = blockIdx.x & 1;
    int cid  = blockIdx.x >> 1;
    int dir  = cid >> 4;
    int b    = cid & 15;

    int u  = rank * 64 + warp * 4 + c;
    int r  = g * 128 + u;

    const float* wh = dir ? whb : whf;
    const u64* wrow = (const u64*)(wh + (size_t)r * HID) + half * 32;
    u64 wr[32];
    #pragma unroll
    for (int p = 0; p < 32; p++) wr[p] = wrow[p];

    unsigned h_lo[2], mb_lo[2], h_pe[2], mb_pe[2];
    h_lo[0] = smem_u32(&hf[0][0]); h_lo[1] = smem_u32(&hf[1][0]);
    mb_lo[0] = smem_u32(&mbar[0]); mb_lo[1] = smem_u32(&mbar[1]);
    int peer = rank ^ 1;
    #pragma unroll
    for (int i = 0; i < 2; i++){
        asm("mapa.shared::cluster.u32 %0, %1, %2;" : "=r"(h_pe[i])  : "r"(h_lo[i]),  "r"(peer));
        asm("mapa.shared::cluster.u32 %0, %1, %2;" : "=r"(mb_pe[i]) : "r"(mb_lo[i]), "r"(peer));
    }

    if (tid < 2 * HPAD) ((float*)hf)[tid] = 0.f;
    if (tid == 0){
        asm volatile("mbarrier.init.shared.b64 [%0], 16;" :: "r"(mb_lo[0]) : "memory");
        asm volatile("mbarrier.init.shared.b64 [%0], 16;" :: "r"(mb_lo[1]) : "memory");
    }
    __syncthreads();
    asm volatile("barrier.cluster.arrive.aligned;" ::: "memory");
    asm volatile("barrier.cluster.wait.aligned;"   ::: "memory");

    // prologue done (independent of producer output) — now wait for xp
    cudaGridDependencySynchronize();

    float cst = 0.f;
    int ph[2] = {0, 0};

    const float* xpd = xp + ((size_t)(dir * BATCH + b)) * LEN * G4 + r;
    bool  is_t = (g == 2);
    float act_m = is_t ? 2.f : 1.f;
    float act_b = is_t ? -1.f : 0.f;
    float pre_m = is_t ? 2.f : 1.f;

    int t  = dir ? (LEN - 1) : 0;
    int dt = dir ? -1 : 1;
    unsigned wr_off = (unsigned)(rank * 68 + warp * 4) * 4u;

    float xg = xpd[t * G4];                       // prefetch step 0

    for (int s = 0; s < LEN; s++){
        float xg_next = (s < LEN - 1) ? xpd[(t + dt) * G4] : 0.f;

        const ulonglong2* hb = (const ulonglong2*)(&hf[s & 1][half * 68]);
        u64 a0 = 0ull, a1 = 0ull;
        #pragma unroll
        for (int i = 0; i < 16; i++){
            ulonglong2 hv = hb[i];
            fma2(a0, wr[2*i],   hv.x);
            fma2(a1, wr[2*i+1], hv.y);
        }
        float2 p0 = unpack2(a0);
        float2 p1 = unpack2(a1);
        float ph_sum = (p0.x + p0.y) + (p1.x + p1.y);
        if (half == 0) ph_sum += xg;
        float pre = ph_sum + __shfl_xor_sync(0xffffffffu, ph_sum, 16);

        float sv  = sigf(pre * pre_m);
        float val = fmaf(act_m, sv, act_b);

        float vi = __shfl_sync(0xffffffffu, val, c);
        float vf = __shfl_sync(0xffffffffu, val, 4 + c);
        float vg = __shfl_sync(0xffffffffu, val, 8 + c);
        float vo = __shfl_sync(0xffffffffu, val, 12 + c);

        cst = vf * cst + vi * vg;
        float hv = vo * tanhf_(cst);

        float h1v = __shfl_sync(0xffffffffu, hv, 1);
        float h2v = __shfl_sync(0xffffffffu, hv, 2);
        float h3v = __shfl_sync(0xffffffffu, hv, 3);
        int nb = (s & 1) ^ 1;
        if (l == 0){
            *(float4*)&hcat[((size_t)b * LEN + t) * D2 + dir * HID + rank * 64 + warp * 4] =
                make_float4(hv, h1v, h2v, h3v);
            if (s < LEN - 1){
                *(float4*)&hf[nb][rank * 68 + warp * 4] = make_float4(hv, h1v, h2v, h3v);
                asm volatile("st.shared::cluster.v4.f32 [%0], {%1,%2,%3,%4};"
                             :: "r"(h_pe[nb] + wr_off), "f"(hv), "f"(h1v), "f"(h2v), "f"(h3v)
                             : "memory");
                asm volatile("mbarrier.arrive.release.cluster.shared::cluster.b64 _, [%0];"
                             :: "r"(mb_pe[nb]) : "memory");
            }
        }
        if (s < LEN - 1){
            __syncthreads();
            unsigned mba = mb_lo[nb];
            unsigned par = (unsigned)ph[nb];
            unsigned done;
            asm volatile(
                "{\n\t.reg .pred p;\n\t"
                "mbarrier.try_wait.parity.acquire.cluster.shared::cta.b64 p, [%1], %2;\n\t"
                "selp.b32 %0, 1, 0, p;\n\t}"
                : "=r"(done) : "r"(mba), "r"(par) : "memory");
            if (!done){
                asm volatile(
                    "{\n\t.reg .pred P1;\n\t"
                    "WL_%=:\n\t"
                    "mbarrier.try_wait.parity.acquire.cluster.shared::cta.b64 P1, [%0], %1, 0x989680;\n\t"
                    "@P1 bra.uni WD_%=;\n\t"
                    "bra.uni WL_%=;\n\t"
                    "WD_%=:\n\t}"
                    :: "r"(mba), "r"(par) : "memory");
            }
            ph[nb] ^= 1;
        }
        t += dt;
        xg = xg_next;
    }

    asm volatile("barrier.cluster.arrive.aligned;" ::: "memory");
    asm volatile("barrier.cluster.wait.aligned;"   ::: "memory");
    cudaTriggerProgrammaticLaunchCompletion();
}

// ---------------- biaffine scorer: tanh(a+bp) = 2/(1+e^-2a * e^-2bp) - 1 ----------------
__global__ __launch_bounds__(128)
void scores_kernel(const float* __restrict__ w2, const float* __restrict__ b2,
                   float* __restrict__ out)
{
    int i  = blockIdx.x;      // 0..127
    int bq = blockIdx.y;      // 0..3
    int j  = threadIdx.x;     // 0..127
    __shared__ float ea_sh[4][100];
    __shared__ float w2_sh[100];
    float bb = b2[0];
    if (j < 100) w2_sh[j] = w2[j];
    cudaGridDependencySynchronize();            // g_a / g_bp ready
    if (j < 100){
        #pragma unroll
        for (int bi = 0; bi < 4; bi++)
            ea_sh[bi][j] = g_a[((size_t)(bq*4+bi) * LEN + i) * 100 + j];
    }
    __syncthreads();
    float wsum = 0.f;
    #pragma unroll 4
    for (int k = 0; k < 100; k++) wsum += w2_sh[k];
    float base = bb - wsum;                     // score = 2*acc - wsum + b2
    for (int bi = 0; bi < 4; bi++){
        int b = bq * 4 + bi;
        const float* ebr = g_bp + ((size_t)b * LEN + j) * 100;
        const float* ear = ea_sh[bi];
        float acc = 0.f;
        #pragma unroll 4
        for (int k = 0; k < 100; k++){
            float prod = ear[k] * ebr[k];
            acc = fmaf(w2_sh[k], __fdividef(1.f, 1.f + prod), acc);
        }
        out[(size_t)(i * LEN + j) * BATCH + b] = fmaf(2.f, acc, base);
    }
}

// ---------------- launch ----------------
static inline void launch_pdl(void* fn, dim3 grid, dim3 block, void** args)
{
    cudaLaunchConfig_t cfg = {};
    cfg.gridDim  = grid;
    cfg.blockDim = block;
    cudaLaunchAttribute attr[1];
    attr[0].id = cudaLaunchAttributeProgrammaticStreamSerialization;
    attr[0].val.programmaticStreamSerializationAllowed = 1;
    cfg.attrs = attr;
    cfg.numAttrs = 1;
    cudaLaunchKernelExC(&cfg, fn, args);
}

extern "C" void kernel_launch(void* const* d_in, const int* in_sizes, int n_in,
                              void* d_out, int out_size)
{
    const int*   widx = (const int*)  d_in[0];
    const int*   pidx = (const int*)  d_in[1];
    const float* wemb = (const float*)d_in[4];
    const float* temb = (const float*)d_in[5];
    const float* w_ih_l0f = (const float*)d_in[6];
    const float* w_hh_l0f = (const float*)d_in[7];
    const float* b_ih_l0f = (const float*)d_in[8];
    const float* b_hh_l0f = (const float*)d_in[9];
    const float* w_ih_l0b = (const float*)d_in[10];
    const float* w_hh_l0b = (const float*)d_in[11];
    const float* b_ih_l0b = (const float*)d_in[12];
    const float* b_hh_l0b = (const float*)d_in[13];
    const float* w_ih_l1f = (const float*)d_in[14];
    const float* w_hh_l1f = (const float*)d_in[15];
    const float* b_ih_l1f = (const float*)d_in[16];
    const float* b_hh_l1f = (const float*)d_in[17];
    const float* w_ih_l1b = (const float*)d_in[18];
    const float* w_hh_l1b = (const float*)d_in[19];
    const float* b_ih_l1b = (const float*)d_in[20];
    const float* b_hh_l1b = (const float*)d_in[21];
    const float* fc1_w = (const float*)d_in[22];
    const float* fc1_b = (const float*)d_in[23];
    const float* fc2_w = (const float*)d_in[24];
    const float* fc2_b = (const float*)d_in[25];
    float* out = (float*)d_out;

    float *p_xp, *p_h0, *p_h1, *p_a, *p_bp;
    cudaGetSymbolAddress((void**)&p_xp,  g_xp);
    cudaGetSymbolAddress((void**)&p_h0,  g_h0);
    cudaGetSymbolAddress((void**)&p_h1,  g_h1);
    cudaGetSymbolAddress((void**)&p_a,   g_a);
    cudaGetSymbolAddress((void**)&p_bp,  g_bp);

    const int M = BATCH * LEN;   // 2048
    float* p_xp1 = p_xp + (size_t)M * G4;
    const float* nul = nullptr;
    const int*   nuli = nullptr;

    // layer 0 input projections with fused embedding gather (first kernel: plain launch)
    gemm64<<<dim3(8, 32, 2), 256>>>(nullptr,
        w_ih_l0f, w_ih_l0b, b_ih_l0f, b_ih_l0b, b_hh_l0f, b_hh_l0b,
        p_xp, p_xp1, G4, EMB, EMB, 0, 1, widx, pidx, wemb, temb);

    {   // lstm layer 0 (PDL)
        void* args[] = {(void*)&p_xp, (void*)&w_hh_l0f, (void*)&w_hh_l0b, (void*)&p_h0};
        launch_pdl((void*)lstm_kernel, dim3(64), dim3(512), args);
    }
    {   // gemm layer 1 (PDL)
        int N_=G4, K_=D2, ws_=D2, ex_=0, de_=0;
        void* args[] = {(void*)&p_h0,
            (void*)&w_ih_l1f, (void*)&w_ih_l1b, (void*)&b_ih_l1f, (void*)&b_ih_l1b,
            (void*)&b_hh_l1f, (void*)&b_hh_l1b, (void*)&p_xp, (void*)&p_xp1,
            (void*)&N_, (void*)&K_, (void*)&ws_, (void*)&ex_, (void*)&de_,
            (void*)&nuli, (void*)&nuli, (void*)&nul, (void*)&nul};
        launch_pdl((void*)gemm64, dim3(8, 32, 2), dim3(256), args);
    }
    {   // lstm layer 1 (PDL)
        void* args[] = {(void*)&p_xp, (void*)&w_hh_l1f, (void*)&w_hh_l1b, (void*)&p_h1};
        launch_pdl((void*)lstm_kernel, dim3(64), dim3(512), args);
    }
    {   // fc1 split projections (PDL), epilogue exp(-2*val)
        const float* fc1_wb = fc1_w + D2;
        int N_=100, K_=D2, ws_=512, ex_=1, de_=0;
        void* args[] = {(void*)&p_h1,
            (void*)&fc1_w, (void*)&fc1_wb, (void*)&nul, (void*)&fc1_b,
            (void*)&nul, (void*)&nul, (void*)&p_a, (void*)&p_bp,
            (void*)&N_, (void*)&K_, (void*)&ws_, (void*)&ex_, (void*)&de_,
            (void*)&nuli, (void*)&nuli, (void*)&nul, (void*)&nul};
        launch_pdl((void*)gemm64, dim3(2, 32, 2), dim3(256), args);
    }
    {   // scores (PDL)
        void* args[] = {(void*)&fc2_w, (void*)&fc2_b, (void*)&out};
        launch_pdl((void*)scores_kernel, dim3(128, 4), dim3(128), args);
    }
    (void)in_sizes; (void)n_in; (void)out_size;
}

// round 17
// speedup vs baseline: 1.1411x; 1.0804x over previous
#include <cuda_runtime.h>
#include <cuda_bf16.h>

#define BATCH 16
#define LEN   128
#define HID   128
#define G4    512   // 4*HID
#define EMB   128
#define D2    256   // 2*HID
#define HPAD  136   // padded h row: halves at +0 and +68 floats

typedef unsigned long long u64;

// ---------------- scratch (device globals; no allocation) ----------------
__device__ float g_xp [2*BATCH*LEN*G4];
__device__ float g_h0 [BATCH*LEN*D2];
__device__ float g_h1 [BATCH*LEN*D2];
__device__ float g_a  [BATCH*LEN*100];   // holds exp(-2*a)
__device__ float g_bp [BATCH*LEN*100];   // holds exp(-2*bp)

// ---------------- helpers ----------------
__device__ __forceinline__ float sigf(float x){
    float e = __expf(-x);
    return __fdividef(1.f, 1.f + e);
}
__device__ __forceinline__ float tanhf_(float x){
    float e = __expf(-2.f * x);
    return __fdividef(2.f, 1.f + e) - 1.f;
}
__device__ __forceinline__ void fma2(u64 &d, u64 a, u64 b){
    asm("fma.rn.f32x2 %0, %1, %2, %0;" : "+l"(d) : "l"(a), "l"(b));
}
__device__ __forceinline__ float2 unpack2(u64 v){
    float2 r; asm("mov.b64 {%0,%1}, %2;" : "=f"(r.x), "=f"(r.y) : "l"(v)); return r;
}
__device__ __forceinline__ u64 dup2(float v){
    u64 r; asm("mov.b64 %0, {%1,%1};" : "=l"(r) : "f"(v)); return r;
}
__device__ __forceinline__ unsigned smem_u32(const void* p){
    unsigned a;
    asm("{ .reg .u64 t; cvta.to.shared.u64 t, %1; cvt.u32.u64 %0, t; }" : "=r"(a) : "l"(p));
    return a;
}

// ---------------- tiled GEMM: proven layout + register-dup FMA2 inner loop ----------------
// C[m][n] = A[m][0:K].W[n][0:K] + b1[n] + b2[n].
// expo:  store exp(-2*val).  do_emb: A-tile gathered from embeddings.
// PDL: waits on upstream grid before first A read; triggers after stores.
__global__ __launch_bounds__(256)
void gemm64(const float* __restrict__ A,
            const float* __restrict__ W0, const float* __restrict__ W1,
            const float* __restrict__ b1_0, const float* __restrict__ b1_1,
            const float* __restrict__ b2_0, const float* __restrict__ b2_1,
            float* __restrict__ C0, float* __restrict__ C1,
            int N, int K, int wstride, int expo, int do_emb,
            const int* __restrict__ widx, const int* __restrict__ pidx,
            const float* __restrict__ wemb, const float* __restrict__ temb)
{
    __shared__ __align__(16) float As[16][68];
    __shared__ __align__(16) float Ws[16][68];
    int z = blockIdx.z;
    const float* W  = z ? W1   : W0;
    const float* b1 = z ? b1_1 : b1_0;
    const float* b2 = z ? b2_1 : b2_0;
    float* C        = z ? C1   : C0;

    int tid = threadIdx.x;
    int tx = tid & 15, ty = tid >> 4;
    int m0 = blockIdx.y * 64, n0 = blockIdx.x * 64;
    int lrow = tid >> 2;
    int lk   = (tid & 3) * 4;

    cudaGridDependencySynchronize();

    int ew = 0, ep = 0;
    if (do_emb){
        int m = m0 + lrow;
        ew = widx[m];
        ep = pidx[m];
    }

    u64 acc[2][4];                      // [m-pair][n], f32x2 over m
    #pragma unroll
    for (int i = 0; i < 2; i++)
        #pragma unroll
        for (int j = 0; j < 4; j++) acc[i][j] = 0ull;

    for (int k0 = 0; k0 < K; k0 += 16){
        int ka = k0 + lk;
        float4 av;
        if (do_emb){
            if (ka < 100) av = *(const float4*)&wemb[(size_t)ew * 100 + ka];
            else          av = *(const float4*)&temb[(size_t)ep * 28 + (ka - 100)];
        } else {
            av = *(const float4*)&A[(size_t)(m0 + lrow) * K + ka];
        }
        int wn = n0 + lrow;
        float4 wv = make_float4(0.f,0.f,0.f,0.f);
        if (wn < N) wv = *(const float4*)&W[(size_t)wn * wstride + ka];
        As[lk+0][lrow] = av.x; As[lk+1][lrow] = av.y; As[lk+2][lrow] = av.z; As[lk+3][lrow] = av.w;
        Ws[lk+0][lrow] = wv.x; Ws[lk+1][lrow] = wv.y; Ws[lk+2][lrow] = wv.z; Ws[lk+3][lrow] = wv.w;
        __syncthreads();
        #pragma unroll
        for (int kk = 0; kk < 16; kk++){
            ulonglong2 am = *(const ulonglong2*)&As[kk][ty*4];   // m pairs (ty*4, ty*4+2)
            float4 w4 = *(const float4*)&Ws[kk][tx*4];
            u64 w0 = dup2(w4.x), w1 = dup2(w4.y), w2 = dup2(w4.z), w3 = dup2(w4.w);
            fma2(acc[0][0], am.x, w0); fma2(acc[0][1], am.x, w1);
            fma2(acc[0][2], am.x, w2); fma2(acc[0][3], am.x, w3);
            fma2(acc[1][0], am.y, w0); fma2(acc[1][1], am.y, w1);
            fma2(acc[1][2], am.y, w2); fma2(acc[1][3], am.y, w3);
        }
        __syncthreads();
    }
    #pragma unroll
    for (int j = 0; j < 4; j++){
        int n = n0 + tx*4 + j;
        if (n >= N) continue;
        float bias = (b1 ? b1[n] : 0.f) + (b2 ? b2[n] : 0.f);
        #pragma unroll
        for (int i = 0; i < 2; i++){
            float2 v = unpack2(acc[i][j]);
            int m = m0 + ty*4 + i*2;
            float v0 = v.x + bias, v1 = v.y + bias;
            C[(size_t)m     * N + n] = expo ? __expf(-2.f * v0) : v0;
            C[(size_t)(m+1) * N + n] = expo ? __expf(-2.f * v1) : v1;
        }
    }
    cudaTriggerProgrammaticLaunchCompletion();
}

// ---------------- LSTM: R13/R15 structure (best measured) + PDL ----------------
// 2-CTA cluster per (dir,batch). Rank owns 64 hidden units (256 gate rows).
// 512 threads: warp=tid>>5, l=tid&31, c=l&3, g=(l>>2)&3, half=l>>4.
// unit u = rank*64 + warp*4 + c ; row r = g*128 + u; 64 k (half) in 32 u64 regs.
// Epilogue cluster-sync removed: cluster smem/mbar lifetime is cluster-wide,
// and the step-(LEN-2) trywait already ordered the last consumed peer data.
__global__ __launch_bounds__(512, 1) __cluster_dims__(2, 1, 1)
void lstm_kernel(const float* __restrict__ xp,   // [2][B][L][512]
                 const float* __restrict__ whf,
                 const float* __restrict__ whb,
                 float* __restrict__ hcat)       // [B][L][256]
{
    __shared__ __align__(16) float hf[2][HPAD];
    __shared__ __align__(8)  u64   mbar[2];

    int tid  = threadIdx.x;
    int warp = tid >> 5;
    int l    = tid & 31;
    int c    = l & 3;
    int g    = (l >> 2) & 3;
    int half = l >> 4;

    int rank = blockIdx.x & 1;
    int cid  = blockIdx.x >> 1;
    int dir  = cid >> 4;
    int b    = cid & 15;

    int u  = rank * 64 + warp * 4 + c;
    int r  = g * 128 + u;

    const float* wh = dir ? whb : whf;
    const u64* wrow = (const u64*)(wh + (size_t)r * HID) + half * 32;
    u64 wr[32];
    #pragma unroll
    for (int p = 0; p < 32; p++) wr[p] = wrow[p];

    unsigned h_lo[2], mb_lo[2], h_pe[2], mb_pe[2];
    h_lo[0] = smem_u32(&hf[0][0]); h_lo[1] = smem_u32(&hf[1][0]);
    mb_lo[0] = smem_u32(&mbar[0]); mb_lo[1] = smem_u32(&mbar[1]);
    int peer = rank ^ 1;
    #pragma unroll
    for (int i = 0; i < 2; i++){
        asm("mapa.shared::cluster.u32 %0, %1, %2;" : "=r"(h_pe[i])  : "r"(h_lo[i]),  "r"(peer));
        asm("mapa.shared::cluster.u32 %0, %1, %2;" : "=r"(mb_pe[i]) : "r"(mb_lo[i]), "r"(peer));
    }

    if (tid < 2 * HPAD) ((float*)hf)[tid] = 0.f;
    if (tid == 0){
        asm volatile("mbarrier.init.shared.b64 [%0], 16;" :: "r"(mb_lo[0]) : "memory");
        asm volatile("mbarrier.init.shared.b64 [%0], 16;" :: "r"(mb_lo[1]) : "memory");
    }
    __syncthreads();
    asm volatile("barrier.cluster.arrive.aligned;" ::: "memory");
    asm volatile("barrier.cluster.wait.aligned;"   ::: "memory");

    // prologue done (independent of producer output) — now wait for xp
    cudaGridDependencySynchronize();

    float cst = 0.f;
    int ph[2] = {0, 0};

    const float* xpd = xp + ((size_t)(dir * BATCH + b)) * LEN * G4 + r;
    bool  is_t = (g == 2);
    float act_m = is_t ? 2.f : 1.f;
    float act_b = is_t ? -1.f : 0.f;
    float pre_m = is_t ? 2.f : 1.f;

    int t  = dir ? (LEN - 1) : 0;
    int dt = dir ? -1 : 1;
    unsigned wr_off = (unsigned)(rank * 68 + warp * 4) * 4u;

    float xg = xpd[t * G4];                       // prefetch step 0

    for (int s = 0; s < LEN; s++){
        float xg_next = (s < LEN - 1) ? xpd[(t + dt) * G4] : 0.f;

        const ulonglong2* hb = (const ulonglong2*)(&hf[s & 1][half * 68]);
        u64 a0 = 0ull, a1 = 0ull;
        #pragma unroll
        for (int i = 0; i < 16; i++){
            ulonglong2 hv = hb[i];
            fma2(a0, wr[2*i],   hv.x);
            fma2(a1, wr[2*i+1], hv.y);
        }
        float2 p0 = unpack2(a0);
        float2 p1 = unpack2(a1);
        float ph_sum = (p0.x + p0.y) + (p1.x + p1.y);
        if (half == 0) ph_sum += xg;
        float pre = ph_sum + __shfl_xor_sync(0xffffffffu, ph_sum, 16);

        float sv  = sigf(pre * pre_m);
        float val = fmaf(act_m, sv, act_b);

        float vi = __shfl_sync(0xffffffffu, val, c);
        float vf = __shfl_sync(0xffffffffu, val, 4 + c);
        float vg = __shfl_sync(0xffffffffu, val, 8 + c);
        float vo = __shfl_sync(0xffffffffu, val, 12 + c);

        cst = vf * cst + vi * vg;
        float hv = vo * tanhf_(cst);

        float h1v = __shfl_sync(0xffffffffu, hv, 1);
        float h2v = __shfl_sync(0xffffffffu, hv, 2);
        float h3v = __shfl_sync(0xffffffffu, hv, 3);
        int nb = (s & 1) ^ 1;
        if (l == 0){
            *(float4*)&hcat[((size_t)b * LEN + t) * D2 + dir * HID + rank * 64 + warp * 4] =
                make_float4(hv, h1v, h2v, h3v);
            if (s < LEN - 1){
                *(float4*)&hf[nb][rank * 68 + warp * 4] = make_float4(hv, h1v, h2v, h3v);
                asm volatile("st.shared::cluster.v4.f32 [%0], {%1,%2,%3,%4};"
                             :: "r"(h_pe[nb] + wr_off), "f"(hv), "f"(h1v), "f"(h2v), "f"(h3v)
                             : "memory");
                asm volatile("mbarrier.arrive.release.cluster.shared::cluster.b64 _, [%0];"
                             :: "r"(mb_pe[nb]) : "memory");
            }
        }
        if (s < LEN - 1){
            __syncthreads();
            unsigned mba = mb_lo[nb];
            unsigned par = (unsigned)ph[nb];
            unsigned done;
            asm volatile(
                "{\n\t.reg .pred p;\n\t"
                "mbarrier.try_wait.parity.acquire.cluster.shared::cta.b64 p, [%1], %2;\n\t"
                "selp.b32 %0, 1, 0, p;\n\t}"
                : "=r"(done) : "r"(mba), "r"(par) : "memory");
            if (!done){
                asm volatile(
                    "{\n\t.reg .pred P1;\n\t"
                    "WL_%=:\n\t"
                    "mbarrier.try_wait.parity.acquire.cluster.shared::cta.b64 P1, [%0], %1, 0x989680;\n\t"
                    "@P1 bra.uni WD_%=;\n\t"
                    "bra.uni WL_%=;\n\t"
                    "WD_%=:\n\t}"
                    :: "r"(mba), "r"(par) : "memory");
            }
            ph[nb] ^= 1;
        }
        t += dt;
        xg = xg_next;
    }

    cudaTriggerProgrammaticLaunchCompletion();
}

// ---------------- biaffine scorer: tanh(a+bp) = 2/(1+e^-2a * e^-2bp) - 1 ----------------
// ebr rows read as float4 (16B-aligned: (b*128+j)*100 ≡ 0 mod 4 floats).
__global__ __launch_bounds__(128)
void scores_kernel(const float* __restrict__ w2, const float* __restrict__ b2,
                   float* __restrict__ out)
{
    int i  = blockIdx.x;      // 0..127
    int bq = blockIdx.y;      // 0..3
    int j  = threadIdx.x;     // 0..127
    __shared__ float ea_sh[4][100];
    __shared__ float w2_sh[100];
    float bb = b2[0];
    if (j < 100) w2_sh[j] = w2[j];
    cudaGridDependencySynchronize();            // g_a / g_bp ready
    if (j < 100){
        #pragma unroll
        for (int bi = 0; bi < 4; bi++)
            ea_sh[bi][j] = g_a[((size_t)(bq*4+bi) * LEN + i) * 100 + j];
    }
    __syncthreads();
    float wsum = 0.f;
    #pragma unroll 4
    for (int k = 0; k < 100; k++) wsum += w2_sh[k];
    float base = bb - wsum;                     // score = 2*acc - wsum + b2
    for (int bi = 0; bi < 4; bi++){
        int b = bq * 4 + bi;
        const float4* ebr4 = (const float4*)(g_bp + ((size_t)b * LEN + j) * 100);
        const float* ear = ea_sh[bi];
        float acc = 0.f;
        #pragma unroll 5
        for (int k4 = 0; k4 < 25; k4++){
            float4 e = ebr4[k4];
            int k = k4 * 4;
            acc = fmaf(w2_sh[k+0], __fdividef(1.f, 1.f + ear[k+0] * e.x), acc);
            acc = fmaf(w2_sh[k+1], __fdividef(1.f, 1.f + ear[k+1] * e.y), acc);
            acc = fmaf(w2_sh[k+2], __fdividef(1.f, 1.f + ear[k+2] * e.z), acc);
            acc = fmaf(w2_sh[k+3], __fdividef(1.f, 1.f + ear[k+3] * e.w), acc);
        }
        out[(size_t)(i * LEN + j) * BATCH + b] = fmaf(2.f, acc, base);
    }
}

// ---------------- launch ----------------
static inline void launch_pdl(void* fn, dim3 grid, dim3 block, void** args)
{
    cudaLaunchConfig_t cfg = {};
    cfg.gridDim  = grid;
    cfg.blockDim = block;
    cudaLaunchAttribute attr[1];
    attr[0].id = cudaLaunchAttributeProgrammaticStreamSerialization;
    attr[0].val.programmaticStreamSerializationAllowed = 1;
    cfg.attrs = attr;
    cfg.numAttrs = 1;
    cudaLaunchKernelExC(&cfg, fn, args);
}

extern "C" void kernel_launch(void* const* d_in, const int* in_sizes, int n_in,
                              void* d_out, int out_size)
{
    const int*   widx = (const int*)  d_in[0];
    const int*   pidx = (const int*)  d_in[1];
    const float* wemb = (const float*)d_in[4];
    const float* temb = (const float*)d_in[5];
    const float* w_ih_l0f = (const float*)d_in[6];
    const float* w_hh_l0f = (const float*)d_in[7];
    const float* b_ih_l0f = (const float*)d_in[8];
    const float* b_hh_l0f = (const float*)d_in[9];
    const float* w_ih_l0b = (const float*)d_in[10];
    const float* w_hh_l0b = (const float*)d_in[11];
    const float* b_ih_l0b = (const float*)d_in[12];
    const float* b_hh_l0b = (const float*)d_in[13];
    const float* w_ih_l1f = (const float*)d_in[14];
    const float* w_hh_l1f = (const float*)d_in[15];
    const float* b_ih_l1f = (const float*)d_in[16];
    const float* b_hh_l1f = (const float*)d_in[17];
    const float* w_ih_l1b = (const float*)d_in[18];
    const float* w_hh_l1b = (const float*)d_in[19];
    const float* b_ih_l1b = (const float*)d_in[20];
    const float* b_hh_l1b = (const float*)d_in[21];
    const float* fc1_w = (const float*)d_in[22];
    const float* fc1_b = (const float*)d_in[23];
    const float* fc2_w = (const float*)d_in[24];
    const float* fc2_b = (const float*)d_in[25];
    float* out = (float*)d_out;

    float *p_xp, *p_h0, *p_h1, *p_a, *p_bp;
    cudaGetSymbolAddress((void**)&p_xp,  g_xp);
    cudaGetSymbolAddress((void**)&p_h0,  g_h0);
    cudaGetSymbolAddress((void**)&p_h1,  g_h1);
    cudaGetSymbolAddress((void**)&p_a,   g_a);
    cudaGetSymbolAddress((void**)&p_bp,  g_bp);

    const int M = BATCH * LEN;   // 2048
    float* p_xp1 = p_xp + (size_t)M * G4;
    const float* nul = nullptr;
    const int*   nuli = nullptr;

    // layer 0 input projections with fused embedding gather (first kernel: plain launch)
    gemm64<<<dim3(8, 32, 2), 256>>>(nullptr,
        w_ih_l0f, w_ih_l0b, b_ih_l0f, b_ih_l0b, b_hh_l0f, b_hh_l0b,
        p_xp, p_xp1, G4, EMB, EMB, 0, 1, widx, pidx, wemb, temb);

    {   // lstm layer 0 (PDL)
        void* args[] = {(void*)&p_xp, (void*)&w_hh_l0f, (void*)&w_hh_l0b, (void*)&p_h0};
        launch_pdl((void*)lstm_kernel, dim3(64), dim3(512), args);
    }
    {   // gemm layer 1 (PDL)
        int N_=G4, K_=D2, ws_=D2, ex_=0, de_=0;
        void* args[] = {(void*)&p_h0,
            (void*)&w_ih_l1f, (void*)&w_ih_l1b, (void*)&b_ih_l1f, (void*)&b_ih_l1b,
            (void*)&b_hh_l1f, (void*)&b_hh_l1b, (void*)&p_xp, (void*)&p_xp1,
            (void*)&N_, (void*)&K_, (void*)&ws_, (void*)&ex_, (void*)&de_,
            (void*)&nuli, (void*)&nuli, (void*)&nul, (void*)&nul};
        launch_pdl((void*)gemm64, dim3(8, 32, 2), dim3(256), args);
    }
    {   // lstm layer 1 (PDL)
        void* args[] = {(void*)&p_xp, (void*)&w_hh_l1f, (void*)&w_hh_l1b, (void*)&p_h1};
        launch_pdl((void*)lstm_kernel, dim3(64), dim3(512), args);
    }
    {   // fc1 split projections (PDL), epilogue exp(-2*val)
        const float* fc1_wb = fc1_w + D2;
        int N_=100, K_=D2, ws_=512, ex_=1, de_=0;
        void* args[] = {(void*)&p_h1,
            (void*)&fc1_w, (void*)&fc1_wb, (void*)&nul, (void*)&fc1_b,
            (void*)&nul, (void*)&nul, (void*)&p_a, (void*)&p_bp,
            (void*)&N_, (void*)&K_, (void*)&ws_, (void*)&ex_, (void*)&de_,
            (void*)&nuli, (void*)&nuli, (void*)&nul, (void*)&nul};
        launch_pdl((void*)gemm64, dim3(2, 32, 2), dim3(256), args);
    }
    {   // scores (PDL)
        void* args[] = {(void*)&fc2_w, (void*)&fc2_b, (void*)&out};
        launch_pdl((void*)scores_kernel, dim3(128, 4), dim3(128), args);
    }
    (void)in_sizes; (void)n_in; (void)out_size;
}